// round 1
// baseline (speedup 1.0000x reference)
#include <cuda_runtime.h>
#include <cuda_bf16.h>
#include <cstddef>

#define N_USERS 100000
#define N_ITEMS 50000
#define N_TOT   150000
#define EMB_D   64
#define NNZ     4800000
#define VEC     (EMB_D / 4)          // 16 float4 per row
#define ROW_F4  (N_TOT * VEC)        // 2.4M float4 per buffer

// Layer output scratch (allowed: __device__ globals, no runtime allocation)
__device__ __align__(256) float g_b1[(size_t)N_TOT * EMB_D];
__device__ __align__(256) float g_b2[(size_t)N_TOT * EMB_D];
__device__ __align__(256) float g_b3[(size_t)N_TOT * EMB_D];

__device__ __forceinline__ void red_add_v4(float* p, float4 v) {
#if __CUDA_ARCH__ >= 900
    asm volatile("red.global.add.v4.f32 [%0], {%1, %2, %3, %4};"
                 :: "l"(p), "f"(v.x), "f"(v.y), "f"(v.z), "f"(v.w)
                 : "memory");
#else
    atomicAdd(p + 0, v.x);
    atomicAdd(p + 1, v.y);
    atomicAdd(p + 2, v.z);
    atomicAdd(p + 3, v.w);
#endif
}

// Edge-parallel SpMM: 16 threads per nnz, each handles one float4 of the
// 64-float embedding row. Gather x[col] (L2-resident), scale by val,
// scatter-reduce into out[row] via RED.128 (no return value, no ordering wait).
// Source addressing is split (ubase/ibase) so layer 1 can read the two input
// tensors directly without a concat copy; later layers pass
// (buf, buf + N_USERS*64) which degenerates to a single contiguous buffer.
__global__ __launch_bounds__(256) void spmm_red_kernel(
    const int*   __restrict__ row,
    const int*   __restrict__ col,
    const float* __restrict__ vals,
    const float* __restrict__ ubase,
    const float* __restrict__ ibase,
    float*       __restrict__ out)
{
    int t    = blockIdx.x * blockDim.x + threadIdx.x;
    int e    = t >> 4;          // edge index
    int lane = t & 15;          // float4 slot within the 64-float row
    if (e >= NNZ) return;

    int   r = row[e];
    int   c = col[e];
    float v = vals[e];

    const float* src = (c < N_USERS)
        ? (ubase + (size_t)c * EMB_D)
        : (ibase + (size_t)(c - N_USERS) * EMB_D);

    float4 x = reinterpret_cast<const float4*>(src)[lane];
    x.x *= v; x.y *= v; x.z *= v; x.w *= v;

    red_add_v4(out + (size_t)r * EMB_D + (size_t)lane * 4, x);
}

// Fused epilogue: out = (e0 + b1 + b2 + b3) * 0.25, with e0 read directly
// from the user/item input tensors (concat view).
__global__ __launch_bounds__(256) void final_mean_kernel(
    const float* __restrict__ u,
    const float* __restrict__ it,
    const float* __restrict__ b1,
    const float* __restrict__ b2,
    const float* __restrict__ b3,
    float*       __restrict__ out)
{
    int i = blockIdx.x * blockDim.x + threadIdx.x;   // float4 index
    if (i >= ROW_F4) return;

    const int uf4 = N_USERS * VEC;
    float4 a = (i < uf4)
        ? reinterpret_cast<const float4*>(u)[i]
        : reinterpret_cast<const float4*>(it)[i - uf4];
    float4 x1 = reinterpret_cast<const float4*>(b1)[i];
    float4 x2 = reinterpret_cast<const float4*>(b2)[i];
    float4 x3 = reinterpret_cast<const float4*>(b3)[i];

    float4 o;
    o.x = 0.25f * (a.x + x1.x + x2.x + x3.x);
    o.y = 0.25f * (a.y + x1.y + x2.y + x3.y);
    o.z = 0.25f * (a.z + x1.z + x2.z + x3.z);
    o.w = 0.25f * (a.w + x1.w + x2.w + x3.w);

    reinterpret_cast<float4*>(out)[i] = o;
}

extern "C" void kernel_launch(void* const* d_in, const int* in_sizes, int n_in,
                              void* d_out, int out_size)
{
    const float* user_emb = (const float*)d_in[0];   // (100000, 64) f32
    const float* item_emb = (const float*)d_in[1];   // (50000, 64)  f32
    const int*   adj_row  = (const int*)  d_in[2];   // (4800000,)   i32
    const int*   adj_col  = (const int*)  d_in[3];   // (4800000,)   i32
    const float* adj_vals = (const float*)d_in[4];   // (4800000,)   f32
    float*       out      = (float*)d_out;           // (150000, 64) f32

    float *b1, *b2, *b3;
    cudaGetSymbolAddress((void**)&b1, g_b1);
    cudaGetSymbolAddress((void**)&b2, g_b2);
    cudaGetSymbolAddress((void**)&b3, g_b3);

    const size_t buf_bytes = (size_t)N_TOT * EMB_D * sizeof(float);
    const int spmm_threads = 256;
    const int spmm_blocks  = (NNZ * 16 + spmm_threads - 1) / spmm_threads;
    const int fin_threads  = 256;
    const int fin_blocks   = (ROW_F4 + fin_threads - 1) / fin_threads;

    // Layer 1: gather directly from the two input tensors
    cudaMemsetAsync(b1, 0, buf_bytes, 0);
    spmm_red_kernel<<<spmm_blocks, spmm_threads>>>(
        adj_row, adj_col, adj_vals, user_emb, item_emb, b1);

    // Layer 2
    cudaMemsetAsync(b2, 0, buf_bytes, 0);
    spmm_red_kernel<<<spmm_blocks, spmm_threads>>>(
        adj_row, adj_col, adj_vals, b1, b1 + (size_t)N_USERS * EMB_D, b2);

    // Layer 3
    cudaMemsetAsync(b3, 0, buf_bytes, 0);
    spmm_red_kernel<<<spmm_blocks, spmm_threads>>>(
        adj_row, adj_col, adj_vals, b2, b2 + (size_t)N_USERS * EMB_D, b3);

    // Fused mean over {e0, b1, b2, b3}
    final_mean_kernel<<<fin_blocks, fin_threads>>>(
        user_emb, item_emb, b1, b2, b3, out);
}

// round 2
// speedup vs baseline: 2.4092x; 2.4092x over previous
#include <cuda_runtime.h>
#include <cuda_bf16.h>
#include <cstddef>

#define N_USERS 100000
#define N_ITEMS 50000
#define N_TOT   150000
#define EMB_D   64
#define NNZ     4800000
#define VEC     (EMB_D / 4)          // 16 float4 per row
#define ROW_F4  (N_TOT * VEC)        // 2.4M float4 per buffer
#define SCAN_BLK 1024
#define NB ((N_TOT + SCAN_BLK - 1) / SCAN_BLK)   // 147 scan blocks

// ---- device-global scratch (no runtime allocation allowed) ----
__device__ __align__(256) float g_x0[(size_t)N_TOT * EMB_D];
__device__ __align__(256) float g_b1[(size_t)N_TOT * EMB_D];
__device__ __align__(256) float g_b2[(size_t)N_TOT * EMB_D];
__device__ __align__(256) float g_b3[(size_t)N_TOT * EMB_D];
__device__ __align__(256) int2  g_edges[NNZ];        // sorted (col, val_bits)
__device__ int g_rowptr[N_TOT + 1];
__device__ int g_cnt[N_TOT];
__device__ int g_cur[N_TOT];
__device__ int g_blk[256];

// ---------------- CSR build ----------------

__global__ __launch_bounds__(256) void hist_kernel(const int* __restrict__ row) {
    int e = blockIdx.x * blockDim.x + threadIdx.x;
    if (e < NNZ) atomicAdd(&g_cnt[row[e]], 1);
}

// Per-block exclusive scan of counts; block totals to g_blk.
__global__ __launch_bounds__(SCAN_BLK) void scan_blocks_kernel() {
    __shared__ int s[SCAN_BLK];
    int i = blockIdx.x * SCAN_BLK + threadIdx.x;
    int v = (i < N_TOT) ? g_cnt[i] : 0;
    s[threadIdx.x] = v;
    __syncthreads();
    for (int off = 1; off < SCAN_BLK; off <<= 1) {
        int t = (threadIdx.x >= off) ? s[threadIdx.x - off] : 0;
        __syncthreads();
        s[threadIdx.x] += t;
        __syncthreads();
    }
    if (i < N_TOT) g_rowptr[i] = s[threadIdx.x] - v;   // exclusive
    if (threadIdx.x == SCAN_BLK - 1) g_blk[blockIdx.x] = s[SCAN_BLK - 1];
}

// Single-block exclusive scan of the NB block totals (NB=147 <= 256).
__global__ __launch_bounds__(256) void scan_sums_kernel() {
    __shared__ int s[256];
    int v = (threadIdx.x < NB) ? g_blk[threadIdx.x] : 0;
    s[threadIdx.x] = v;
    __syncthreads();
    for (int off = 1; off < 256; off <<= 1) {
        int t = (threadIdx.x >= off) ? s[threadIdx.x - off] : 0;
        __syncthreads();
        s[threadIdx.x] += t;
        __syncthreads();
    }
    if (threadIdx.x < NB) g_blk[threadIdx.x] = s[threadIdx.x] - v;  // exclusive
}

__global__ __launch_bounds__(256) void add_offsets_kernel() {
    int i = blockIdx.x * blockDim.x + threadIdx.x;
    if (i < N_TOT) {
        int p = g_rowptr[i] + g_blk[i >> 10];
        g_rowptr[i] = p;
        g_cur[i]    = p;
    }
    if (i == 0) g_rowptr[N_TOT] = NNZ;
}

__global__ __launch_bounds__(256) void scatter_kernel(
    const int* __restrict__ row, const int* __restrict__ col,
    const float* __restrict__ vals)
{
    int e = blockIdx.x * blockDim.x + threadIdx.x;
    if (e >= NNZ) return;
    int r = row[e];
    int p = atomicAdd(&g_cur[r], 1);
    g_edges[p] = make_int2(col[e], __float_as_int(vals[e]));
}

// ---------------- atomic-free SpMM: one warp per output row ----------------
__global__ __launch_bounds__(256) void spmm_csr_kernel(
    const float* __restrict__ x, float* __restrict__ out)
{
    int w    = (blockIdx.x * blockDim.x + threadIdx.x) >> 5;  // row
    int lane = threadIdx.x & 31;
    if (w >= N_TOT) return;

    int beg = g_rowptr[w];
    int end = g_rowptr[w + 1];

    float ax = 0.0f, ay = 0.0f;
    int j = beg;
    // unroll-4 for memory-level parallelism over the L2-latency gathers
    for (; j + 4 <= end; j += 4) {
        int2 e0 = g_edges[j + 0];
        int2 e1 = g_edges[j + 1];
        int2 e2 = g_edges[j + 2];
        int2 e3 = g_edges[j + 3];
        float2 v0 = *(const float2*)(x + (size_t)e0.x * EMB_D + lane * 2);
        float2 v1 = *(const float2*)(x + (size_t)e1.x * EMB_D + lane * 2);
        float2 v2 = *(const float2*)(x + (size_t)e2.x * EMB_D + lane * 2);
        float2 v3 = *(const float2*)(x + (size_t)e3.x * EMB_D + lane * 2);
        float s0 = __int_as_float(e0.y), s1 = __int_as_float(e1.y);
        float s2 = __int_as_float(e2.y), s3 = __int_as_float(e3.y);
        ax += s0 * v0.x + s1 * v1.x + s2 * v2.x + s3 * v3.x;
        ay += s0 * v0.y + s1 * v1.y + s2 * v2.y + s3 * v3.y;
    }
    for (; j < end; ++j) {
        int2 e = g_edges[j];
        float2 v = *(const float2*)(x + (size_t)e.x * EMB_D + lane * 2);
        float s = __int_as_float(e.y);
        ax += s * v.x;
        ay += s * v.y;
    }

    float2 o; o.x = ax; o.y = ay;
    *(float2*)(out + (size_t)w * EMB_D + lane * 2) = o;
}

// ---------------- fused mean epilogue ----------------
__global__ __launch_bounds__(256) void final_mean_kernel(float* __restrict__ out)
{
    int i = blockIdx.x * blockDim.x + threadIdx.x;   // float4 index
    if (i >= ROW_F4) return;
    float4 a  = reinterpret_cast<const float4*>(g_x0)[i];
    float4 x1 = reinterpret_cast<const float4*>(g_b1)[i];
    float4 x2 = reinterpret_cast<const float4*>(g_b2)[i];
    float4 x3 = reinterpret_cast<const float4*>(g_b3)[i];
    float4 o;
    o.x = 0.25f * (a.x + x1.x + x2.x + x3.x);
    o.y = 0.25f * (a.y + x1.y + x2.y + x3.y);
    o.z = 0.25f * (a.z + x1.z + x2.z + x3.z);
    o.w = 0.25f * (a.w + x1.w + x2.w + x3.w);
    reinterpret_cast<float4*>(out)[i] = o;
}

extern "C" void kernel_launch(void* const* d_in, const int* in_sizes, int n_in,
                              void* d_out, int out_size)
{
    const float* user_emb = (const float*)d_in[0];
    const float* item_emb = (const float*)d_in[1];
    const int*   adj_row  = (const int*)  d_in[2];
    const int*   adj_col  = (const int*)  d_in[3];
    const float* adj_vals = (const float*)d_in[4];
    float*       out      = (float*)d_out;

    float *x0, *b1, *b2, *b3;
    int *cnt;
    cudaGetSymbolAddress((void**)&x0,  g_x0);
    cudaGetSymbolAddress((void**)&b1,  g_b1);
    cudaGetSymbolAddress((void**)&b2,  g_b2);
    cudaGetSymbolAddress((void**)&b3,  g_b3);
    cudaGetSymbolAddress((void**)&cnt, g_cnt);

    const int T = 256;
    const int edge_blocks = (NNZ + T - 1) / T;
    const int node_blocks = (N_TOT + T - 1) / T;
    const int spmm_blocks = (N_TOT * 32 + T - 1) / T;   // warp per row
    const int fin_blocks  = (ROW_F4 + T - 1) / T;

    // contiguous layer-0 embedding
    cudaMemcpyAsync(x0, user_emb, (size_t)N_USERS * EMB_D * sizeof(float),
                    cudaMemcpyDeviceToDevice, 0);
    cudaMemcpyAsync(x0 + (size_t)N_USERS * EMB_D, item_emb,
                    (size_t)N_ITEMS * EMB_D * sizeof(float),
                    cudaMemcpyDeviceToDevice, 0);

    // on-device CSR build
    cudaMemsetAsync(cnt, 0, (size_t)N_TOT * sizeof(int), 0);
    hist_kernel<<<edge_blocks, T>>>(adj_row);
    scan_blocks_kernel<<<NB, SCAN_BLK>>>();
    scan_sums_kernel<<<1, 256>>>();
    add_offsets_kernel<<<node_blocks, T>>>();
    scatter_kernel<<<edge_blocks, T>>>(adj_row, adj_col, adj_vals);

    // 3 atomic-free SpMM layers
    spmm_csr_kernel<<<spmm_blocks, T>>>(x0, b1);
    spmm_csr_kernel<<<spmm_blocks, T>>>(b1, b2);
    spmm_csr_kernel<<<spmm_blocks, T>>>(b2, b3);

    // fused mean
    final_mean_kernel<<<fin_blocks, T>>>(out);
}